// round 1
// baseline (speedup 1.0000x reference)
#include <cuda_runtime.h>

#define CH_IN 32
#define CH_Y  16
#define WDIM  256
#define PLANE (256*256)

__global__ __launch_bounds__(256, 2)
void cross_modal_attn_kernel(
    const float* __restrict__ c,  const float* __restrict__ p,
    const float* __restrict__ Wq, const float* __restrict__ bq,
    const float* __restrict__ Wk, const float* __restrict__ bk,
    const float* __restrict__ Wv, const float* __restrict__ bv,
    const float* __restrict__ Wy, const float* __restrict__ by,
    float* __restrict__ out)
{
    const int tid = threadIdx.x;      // = w, 0..255
    const int h   = blockIdx.x;       // 0..255
    const int b   = blockIdx.y;       // 0..15

    __shared__ float sWq[CH_Y*CH_IN], sWk[CH_Y*CH_IN], sWv[CH_Y*CH_IN];
    __shared__ float sWy[CH_IN*CH_Y];
    __shared__ float sbq[CH_Y], sbk[CH_Y], sbv[CH_Y], sby[CH_IN];
    __shared__ float sred[CH_Y][9];   // [channel][warp], padded
    __shared__ float sfin[CH_Y];

    // cooperative weight staging (512 elems each, 256 threads -> 2 per thread)
    for (int i = tid; i < CH_Y*CH_IN; i += 256) {
        sWq[i] = Wq[i]; sWk[i] = Wk[i]; sWv[i] = Wv[i]; sWy[i] = Wy[i];
    }
    if (tid < CH_Y)  { sbq[tid] = bq[tid]; sbk[tid] = bk[tid]; sbv[tid] = bv[tid]; }
    if (tid < CH_IN) { sby[tid] = by[tid]; }
    __syncthreads();

    const size_t base_in = ((size_t)b * CH_IN) * PLANE + (size_t)h * WDIM + tid;

    // ---- phase 1: p -> k, v ----
    float preg[CH_IN];
#pragma unroll
    for (int ci = 0; ci < CH_IN; ci++) preg[ci] = p[base_in + (size_t)ci * PLANE];

    float kk[CH_Y], vv[CH_Y];
#pragma unroll
    for (int cy = 0; cy < CH_Y; cy++) {
        float ak = sbk[cy], av = sbv[cy];
#pragma unroll
        for (int ci = 0; ci < CH_IN; ci++) {
            float x = preg[ci];
            ak = fmaf(sWk[cy*CH_IN + ci], x, ak);
            av = fmaf(sWv[cy*CH_IN + ci], x, av);
        }
        kk[cy] = ak; vv[cy] = av;
    }

    // ---- phase 2: c -> q, t = q*k ----
    float creg[CH_IN];
#pragma unroll
    for (int ci = 0; ci < CH_IN; ci++) creg[ci] = c[base_in + (size_t)ci * PLANE];

    float t[CH_Y];
#pragma unroll
    for (int cy = 0; cy < CH_Y; cy++) {
        float aq = sbq[cy];
#pragma unroll
        for (int ci = 0; ci < CH_IN; ci++)
            aq = fmaf(sWq[cy*CH_IN + ci], creg[ci], aq);
        t[cy] = aq * kk[cy];
    }

    // ---- softmax over w (256 threads) per channel ----
    const int lane = tid & 31, warp = tid >> 5;

    // max
#pragma unroll
    for (int cy = 0; cy < CH_Y; cy++) {
        float m = t[cy];
#pragma unroll
        for (int o = 16; o; o >>= 1) m = fmaxf(m, __shfl_xor_sync(0xffffffffu, m, o));
        if (lane == 0) sred[cy][warp] = m;
    }
    __syncthreads();
    if (tid < CH_Y) {
        float m = sred[tid][0];
#pragma unroll
        for (int wi = 1; wi < 8; wi++) m = fmaxf(m, sred[tid][wi]);
        sfin[tid] = m;
    }
    __syncthreads();

#pragma unroll
    for (int cy = 0; cy < CH_Y; cy++) t[cy] = __expf(t[cy] - sfin[cy]);

    // sum
#pragma unroll
    for (int cy = 0; cy < CH_Y; cy++) {
        float s = t[cy];
#pragma unroll
        for (int o = 16; o; o >>= 1) s += __shfl_xor_sync(0xffffffffu, s, o);
        if (lane == 0) sred[cy][warp] = s;
    }
    __syncthreads();
    if (tid < CH_Y) {
        float s = 0.0f;
#pragma unroll
        for (int wi = 0; wi < 8; wi++) s += sred[tid][wi];
        sfin[tid] = 1.0f / s;
    }
    __syncthreads();

    float ya[CH_Y];
#pragma unroll
    for (int cy = 0; cy < CH_Y; cy++) ya[cy] = t[cy] * sfin[cy] * vv[cy];

    // ---- output conv 16->32 + concat c ----
    const size_t base_out = ((size_t)b * (2*CH_IN)) * PLANE + (size_t)h * WDIM + tid;
#pragma unroll
    for (int co = 0; co < CH_IN; co++) {
        float a = sby[co];
#pragma unroll
        for (int cy = 0; cy < CH_Y; cy++)
            a = fmaf(sWy[co*CH_Y + cy], ya[cy], a);
        out[base_out + (size_t)co * PLANE] = a;
        out[base_out + (size_t)(CH_IN + co) * PLANE] = creg[co];
    }
}

extern "C" void kernel_launch(void* const* d_in, const int* in_sizes, int n_in,
                              void* d_out, int out_size)
{
    const float* c  = (const float*)d_in[0];
    const float* p  = (const float*)d_in[1];
    const float* Wq = (const float*)d_in[2];
    const float* bq = (const float*)d_in[3];
    const float* Wk = (const float*)d_in[4];
    const float* bk = (const float*)d_in[5];
    const float* Wv = (const float*)d_in[6];
    const float* bv = (const float*)d_in[7];
    const float* Wy = (const float*)d_in[8];
    const float* by = (const float*)d_in[9];
    float* out = (float*)d_out;

    dim3 grid(256, 16);   // (H, B)
    dim3 block(256);      // one thread per w
    cross_modal_attn_kernel<<<grid, block>>>(c, p, Wq, bq, Wk, bk, Wv, bv, Wy, by, out);
}